// round 14
// baseline (speedup 1.0000x reference)
#include <cuda_runtime.h>
#include <cuda_fp16.h>
#include <math.h>
#include <stdint.h>

#define NN 50000
#define NP (NN + 128)
#define NE 400000
#define H  256
#define H3 768
#define NL 8

#define BM 128
#define BN 64
#define BK 32
#define NCH 8

// smem: rows padded to 80B -> conflict-free ldmatrix
#define LDA 80
#define ASPL (128 * LDA)             // 10240 per A plane
#define WSPL (64 * LDA)              // 5120 per W plane
#define OFF_W (2 * ASPL)             // 20480
#define STAGE (2 * ASPL + 2 * WSPL)  // 30720
#define SMEM_TOT (2 * STAGE)         // 61440

#define ASCALE (1.0f / 4096.0f)      // A-side pre-scale (2^-12)
#define LOSC   2048.0f               // lo-plane boost (2^11)

// ---------------- scratch (static device globals) --------------------------
__device__ float g_h1[NN * H];
__device__ float g_gi[NN * H3];
__device__ float g_gh[NN * H3];
__device__ float g_m0[H3 * H];
__device__ float g_c0[H3];

__device__ __half g_xs[2][NP * H];   // gi-input splits (scaled by 2^-12)
__device__ __half g_aggs[2][NP * H]; // agg splits (scaled, compacted)
__device__ __half g_ws[8 * H3 * H];  // 4 W mats x 2 planes (unscaled)

__device__ int g_depth[NN];
__device__ int g_indeg[NN];
__device__ int g_csr_off[NN + 1];
__device__ int g_csr_fill[NN];
__device__ int g_csr_src[NE];
__device__ int g_order[NN];
__device__ int g_cnt[NL];
__device__ int g_off[NL + 1];
__device__ int g_fill[NL];

// ---------------- helpers ---------------------------------------------------
__device__ __forceinline__ uint32_t smem_u32(const void* p) {
    uint32_t a;
    asm("{ .reg .u64 t; cvta.to.shared.u64 t, %1; cvt.u32.u64 %0, t; }" : "=r"(a) : "l"(p));
    return a;
}
__device__ __forceinline__ void ldsm4(uint32_t& r0, uint32_t& r1, uint32_t& r2, uint32_t& r3,
                                      uint32_t a) {
    asm volatile("ldmatrix.sync.aligned.m8n8.x4.shared.b16 {%0,%1,%2,%3}, [%4];"
                 : "=r"(r0), "=r"(r1), "=r"(r2), "=r"(r3) : "r"(a));
}
__device__ __forceinline__ void mma16816(float* d, const uint32_t* a, const uint32_t* b) {
    asm volatile(
        "mma.sync.aligned.m16n8k16.row.col.f32.f16.f16.f32 "
        "{%0,%1,%2,%3}, {%4,%5,%6,%7}, {%8,%9}, {%0,%1,%2,%3};"
        : "+f"(d[0]), "+f"(d[1]), "+f"(d[2]), "+f"(d[3])
        : "r"(a[0]), "r"(a[1]), "r"(a[2]), "r"(a[3]), "r"(b[0]), "r"(b[1]));
}
__device__ __forceinline__ void cp16(uint32_t s, const void* g) {
    asm volatile("cp.async.ca.shared.global [%0], [%1], 16;" :: "r"(s), "l"(g) : "memory");
}
// 2-way fp16 split with pre-scale: h = rn(x*pre), l = rn((x*pre - h)*2048)
__device__ __forceinline__ void split2s(float x, float pre, __half& h, __half& l) {
    float xs = x * pre;
    h = __float2half_rn(xs);
    l = __float2half_rn((xs - __half2float(h)) * LOSC);
}
__device__ __forceinline__ uint32_t pack2h(__half a, __half b) {
    return (uint32_t)__half_as_ushort(b) << 16 | __half_as_ushort(a);
}

// ---------------- schedule construction ------------------------------------
__global__ void k_init() {
    int i = blockIdx.x * blockDim.x + threadIdx.x;
    int stride = gridDim.x * blockDim.x;
    for (int n = i; n < NN; n += stride) {
        g_depth[n] = 0; g_indeg[n] = 0; g_csr_fill[n] = 0;
    }
    if (i < NL) { g_cnt[i] = 0; g_fill[i] = 0; }
}
__global__ void k_relax(const int* __restrict__ E) {
    int i = blockIdx.x * blockDim.x + threadIdx.x;
    int stride = gridDim.x * blockDim.x;
    for (int e = i; e < NE; e += stride) {
        int s = E[e], d = E[NE + e];
        atomicMax(&g_depth[d], g_depth[s] + 1);
    }
}
__global__ void k_indeg(const int* __restrict__ E) {
    int i = blockIdx.x * blockDim.x + threadIdx.x;
    int stride = gridDim.x * blockDim.x;
    for (int e = i; e < NE; e += stride) atomicAdd(&g_indeg[E[NE + e]], 1);
}
__global__ void k_count() {
    int i = blockIdx.x * blockDim.x + threadIdx.x;
    int stride = gridDim.x * blockDim.x;
    for (int n = i; n < NN; n += stride) atomicAdd(&g_cnt[g_depth[n]], 1);
}
__global__ void k_off8() {
    g_off[0] = 0;
    for (int d = 0; d < NL; d++) g_off[d + 1] = g_off[d] + g_cnt[d];
}
__global__ void k_scan() {
    __shared__ int sh[1024];
    __shared__ int carry;
    int tid = threadIdx.x;
    if (tid == 0) carry = 0;
    __syncthreads();
    for (int base = 0; base < NN; base += 1024) {
        int i = base + tid;
        int v = (i < NN) ? g_indeg[i] : 0;
        sh[tid] = v;
        __syncthreads();
        for (int ofs = 1; ofs < 1024; ofs <<= 1) {
            int t = (tid >= ofs) ? sh[tid - ofs] : 0;
            __syncthreads();
            sh[tid] += t;
            __syncthreads();
        }
        if (i < NN) g_csr_off[i] = carry + sh[tid] - v;
        __syncthreads();
        if (tid == 0) carry += sh[1023];
        __syncthreads();
    }
    if (tid == 0) g_csr_off[NN] = carry;
}
__global__ void k_scatter_node() {
    int i = blockIdx.x * blockDim.x + threadIdx.x;
    int stride = gridDim.x * blockDim.x;
    for (int n = i; n < NN; n += stride) {
        int d = g_depth[n];
        int pos = g_off[d] + atomicAdd(&g_fill[d], 1);
        g_order[pos] = n;
    }
}
__global__ void k_scatter_edge(const int* __restrict__ E) {
    int i = blockIdx.x * blockDim.x + threadIdx.x;
    int stride = gridDim.x * blockDim.x;
    for (int e = i; e < NE; e += stride) {
        int d = E[NE + e];
        int pos = g_csr_off[d] + atomicAdd(&g_csr_fill[d], 1);
        g_csr_src[pos] = E[e];
    }
}

// ---------------- fused-weight precompute + splits ---------------------------
__global__ void k_prep(const float* __restrict__ wih0, const float* __restrict__ dw) {
    __shared__ float wrow[H];
    int n = blockIdx.x;
    int j = threadIdx.x;
    wrow[j] = wih0[(size_t)n * H + j];
    __syncthreads();
    float acc = 0.f;
    #pragma unroll 8
    for (int k = 0; k < H; k++) acc = fmaf(wrow[k], dw[(size_t)k * H + j], acc);
    g_m0[(size_t)n * H + j] = acc;
}
__global__ void k_prep_c(const float* __restrict__ wih0, const float* __restrict__ db,
                         const float* __restrict__ bih0) {
    int n = blockIdx.x * blockDim.x + threadIdx.x;
    if (n < H3) {
        float a = 0.f;
        #pragma unroll 8
        for (int k = 0; k < H; k++) a = fmaf(wih0[(size_t)n * H + k], db[k], a);
        g_c0[n] = a + bih0[n];
    }
}
// fp32 -> 2 fp16 planes with pre-scale (n4 = elements/4)
__global__ void k_split(const float* __restrict__ src,
                        __half* __restrict__ dh, __half* __restrict__ dl,
                        float pre, int n4) {
    int i = blockIdx.x * blockDim.x + threadIdx.x;
    int stride = gridDim.x * blockDim.x;
    for (; i < n4; i += stride) {
        float4 f = ((const float4*)src)[i];
        __half h[4], l[4];
        split2s(f.x, pre, h[0], l[0]);
        split2s(f.y, pre, h[1], l[1]);
        split2s(f.z, pre, h[2], l[2]);
        split2s(f.w, pre, h[3], l[3]);
        uint2 uh = {pack2h(h[0], h[1]), pack2h(h[2], h[3])};
        uint2 ul = {pack2h(l[0], l[1]), pack2h(l[2], l[3])};
        ((uint2*)dh)[i] = uh;
        ((uint2*)dl)[i] = ul;
    }
}

// ---------------- fp16 GEMM, 2-plane scaled operands, 3 products ------------
// true C = (accHH*4096 + accLO*2) + bias  (A pre-scaled 2^-12, lo planes x2048)
// row(m) = order[aoff+m] if order else aoff+m (A gather + C scatter by row).
__global__ void __launch_bounds__(256, 2)
gemm_mma(const __half* __restrict__ Ah, const __half* __restrict__ Al,
         const __half* __restrict__ Wh, const __half* __restrict__ Wl,
         const float* __restrict__ bias, float* __restrict__ C,
         const int* __restrict__ order,
         const int* __restrict__ offPtr, const int* __restrict__ cntPtr,
         int Mfixed, int Ncols)
{
    extern __shared__ __align__(128) char smem[];
    const uint32_t sb = smem_u32(smem);

    const int tid = threadIdx.x;
    const int lane = tid & 31;
    const int wid = tid >> 5;
    const int wm = wid & 3;
    const int wn = wid >> 2;

    const int M = cntPtr ? *cntPtr : Mfixed;
    const int aoff = offPtr ? *offPtr : 0;
    const int mtiles = (M + 127) >> 7;
    const int ntiles = Ncols >> 6;
    const int total = mtiles * ntiles;

    const __half* pA[2] = {Ah, Al};
    const __half* pW[2] = {Wh, Wl};

    uint32_t sA[4]; int rA[4], qA[4], plA[4];
    #pragma unroll
    for (int i = 0; i < 4; i++) {
        int u = i * 256 + tid;
        plA[i] = u >> 9; int rem = u & 511; rA[i] = rem >> 2; qA[i] = rem & 3;
        sA[i] = (uint32_t)(plA[i] * ASPL + rA[i] * LDA + qA[i] * 16);
    }
    uint32_t sW[2]; int rW[2], qW[2], plW[2];
    #pragma unroll
    for (int i = 0; i < 2; i++) {
        int u = i * 256 + tid;
        plW[i] = u >> 8; int rem = u & 255; rW[i] = rem >> 2; qW[i] = rem & 3;
        sW[i] = (uint32_t)(OFF_W + plW[i] * WSPL + rW[i] * LDA + qW[i] * 16);
    }

    uint32_t a_ld[2];
    #pragma unroll
    for (int mt = 0; mt < 2; mt++) {
        int r = wm * 32 + mt * 16 + (lane & 15);
        a_ld[mt] = sb + (uint32_t)(r * LDA + (lane >> 4) * 16);
    }
    uint32_t w_ld[2];
    #pragma unroll
    for (int bp = 0; bp < 2; bp++) {
        int n = wn * 32 + bp * 16 + (lane >> 4) * 8 + (lane & 7);
        int half = (lane >> 3) & 1;
        w_ld[bp] = sb + (uint32_t)(OFF_W + n * LDA + half * 16);
    }

    for (int t = blockIdx.x; t < total; t += gridDim.x) {
        int tm = t % mtiles, tn = t / mtiles;
        int row0 = tm << 7, cb = tn << 6;

        const __half* gA[4];
        #pragma unroll
        for (int i = 0; i < 4; i++) {
            int gm = row0 + rA[i];
            int src = (gm < M) ? (order ? order[aoff + gm] : (aoff + gm)) : 0;
            gA[i] = pA[plA[i]] + (size_t)src * H + qA[i] * 8;
        }
        const __half* gW[2];
        #pragma unroll
        for (int i = 0; i < 2; i++)
            gW[i] = pW[plW[i]] + (size_t)(cb + rW[i]) * H + qW[i] * 8;

        #pragma unroll
        for (int i = 0; i < 4; i++) cp16(sb + sA[i], gA[i]);
        #pragma unroll
        for (int i = 0; i < 2; i++) cp16(sb + sW[i], gW[i]);
        asm volatile("cp.async.commit_group;" ::: "memory");
        asm volatile("cp.async.wait_group 0;" ::: "memory");
        __syncthreads();

        float accHH[2][4][4] = {};
        float accLO[2][4][4] = {};

        #pragma unroll 1
        for (int kc = 0; kc < NCH; kc++) {
            uint32_t st = (uint32_t)((kc & 1) * STAGE);
            if (kc < NCH - 1) {
                uint32_t stn = (uint32_t)(((kc + 1) & 1) * STAGE);
                #pragma unroll
                for (int i = 0; i < 4; i++) cp16(sb + stn + sA[i], gA[i] + (kc + 1) * 32);
                #pragma unroll
                for (int i = 0; i < 2; i++) cp16(sb + stn + sW[i], gW[i] + (kc + 1) * 32);
                asm volatile("cp.async.commit_group;" ::: "memory");
            }
            #pragma unroll
            for (int ks = 0; ks < 2; ks++) {
                uint32_t bf[2][4][2];
                #pragma unroll
                for (int s = 0; s < 2; s++) {
                    #pragma unroll
                    for (int bp = 0; bp < 2; bp++) {
                        uint32_t wd = w_ld[bp] + st + ks * 32 + (uint32_t)s * WSPL;
                        uint32_t r0, r1, r2, r3;
                        ldsm4(r0, r1, r2, r3, wd);
                        bf[s][bp * 2][0] = r0;  bf[s][bp * 2][1] = r1;
                        bf[s][bp * 2 + 1][0] = r2;  bf[s][bp * 2 + 1][1] = r3;
                    }
                }
                // A hi: HH fresh + HL chained
                {
                    uint32_t af[2][4];
                    #pragma unroll
                    for (int mt = 0; mt < 2; mt++) {
                        uint32_t ad = a_ld[mt] + st + ks * 32;
                        ldsm4(af[mt][0], af[mt][1], af[mt][2], af[mt][3], ad);
                    }
                    #pragma unroll
                    for (int mt = 0; mt < 2; mt++)
                        #pragma unroll
                        for (int nt = 0; nt < 4; nt++) {
                            float tmp[4] = {0.f, 0.f, 0.f, 0.f};
                            mma16816(tmp, af[mt], bf[0][nt]);
                            accHH[mt][nt][0] += tmp[0];
                            accHH[mt][nt][1] += tmp[1];
                            accHH[mt][nt][2] += tmp[2];
                            accHH[mt][nt][3] += tmp[3];
                            mma16816(accLO[mt][nt], af[mt], bf[1][nt]);
                        }
                }
                // A lo: LH chained
                {
                    uint32_t af[2][4];
                    #pragma unroll
                    for (int mt = 0; mt < 2; mt++) {
                        uint32_t ad = a_ld[mt] + st + ks * 32 + (uint32_t)ASPL;
                        ldsm4(af[mt][0], af[mt][1], af[mt][2], af[mt][3], ad);
                    }
                    #pragma unroll
                    for (int mt = 0; mt < 2; mt++)
                        #pragma unroll
                        for (int nt = 0; nt < 4; nt++)
                            mma16816(accLO[mt][nt], af[mt], bf[0][nt]);
                }
            }
            if (kc < NCH - 1) {
                asm volatile("cp.async.wait_group 0;" ::: "memory");
                __syncthreads();
            }
        }

        // epilogue: (HH*4096 + LO*2) + bias
        #pragma unroll
        for (int mt = 0; mt < 2; mt++) {
            #pragma unroll
            for (int p = 0; p < 2; p++) {
                int gm = row0 + wm * 32 + mt * 16 + (lane >> 2) + p * 8;
                if (gm < M) {
                    int cr = order ? order[aoff + gm] : (aoff + gm);
                    float* dst = C + (size_t)cr * Ncols;
                    #pragma unroll
                    for (int nt = 0; nt < 4; nt++) {
                        int col = cb + wn * 32 + nt * 8 + (lane & 3) * 2;
                        float2 o;
                        o.x = fmaf(accHH[mt][nt][p * 2 + 0], 4096.0f,
                                   accLO[mt][nt][p * 2 + 0] * 2.0f) + __ldg(bias + col);
                        o.y = fmaf(accHH[mt][nt][p * 2 + 1], 4096.0f,
                                   accLO[mt][nt][p * 2 + 1] * 2.0f) + __ldg(bias + col + 1);
                        *(float2*)(dst + col) = o;
                    }
                }
            }
        }
    }
}

// ---------------- per-sweep aggregation: scaled split planes only -----------
__device__ __forceinline__ void store_split4(size_t off, float4 f) {
    __half h[4], l[4];
    split2s(f.x, ASCALE, h[0], l[0]);
    split2s(f.y, ASCALE, h[1], l[1]);
    split2s(f.z, ASCALE, h[2], l[2]);
    split2s(f.w, ASCALE, h[3], l[3]);
    uint2 uh = {pack2h(h[0], h[1]), pack2h(h[2], h[3])};
    uint2 ul = {pack2h(l[0], l[1]), pack2h(l[2], l[3])};
    *(uint2*)(g_aggs[0] + off) = uh;
    *(uint2*)(g_aggs[1] + off) = ul;
}
__global__ void k_gather(const float* __restrict__ hsrc, int sweep) {
    int gw = (blockIdx.x * blockDim.x + threadIdx.x) >> 5;
    int nw = (gridDim.x * blockDim.x) >> 5;
    int lane = threadIdx.x & 31;
    int cnt = g_cnt[sweep], base = g_off[sweep];
    for (int i = gw; i < cnt; i += nw) {
        int node = g_order[base + i];
        int e0 = g_csr_off[node], e1 = g_csr_off[node + 1];
        float4 a0 = make_float4(0.f, 0.f, 0.f, 0.f);
        float4 a1 = make_float4(0.f, 0.f, 0.f, 0.f);
        for (int e = e0; e < e1; e++) {
            int src = g_csr_src[e];
            const float4* r = (const float4*)(hsrc + (size_t)src * H);
            float4 x0 = r[lane], x1 = r[lane + 32];
            a0.x += x0.x; a0.y += x0.y; a0.z += x0.z; a0.w += x0.w;
            a1.x += x1.x; a1.y += x1.y; a1.z += x1.z; a1.w += x1.w;
        }
        size_t orow = (size_t)(base + i) * H;
        store_split4(orow + lane * 4, a0);
        store_split4(orow + 128 + lane * 4, a1);
    }
}

// ---------------- per-sweep GRU epilogue ------------------------------------
__global__ void k_gru(float* __restrict__ hout, int sweep,
                      const float* __restrict__ ghp, int per_node, int wsplit) {
    int cnt = g_cnt[sweep], base = g_off[sweep];
    int j = threadIdx.x;
    for (int i = blockIdx.x; i < cnt; i += gridDim.x) {
        int node = g_order[base + i];
        const float* gi = g_gi + (size_t)node * H3;
        const float* gh = per_node ? (ghp + (size_t)(base + i) * H3) : ghp;
        float ir = gi[j], iz = gi[j + H], in_ = gi[j + 2 * H];
        float hr = gh[j], hz = gh[j + H], hn = gh[j + 2 * H];
        float a = 0.f;
        if (per_node) {
            size_t o2 = (size_t)(base + i) * H + j;
            a = __half2float(g_aggs[0][o2]) * 4096.0f
              + __half2float(g_aggs[1][o2]) * 2.0f;
        }
        float r = 1.f / (1.f + expf(-(ir + hr)));
        float z = 1.f / (1.f + expf(-(iz + hz)));
        float n = tanhf(in_ + r * hn);
        float hv = (1.f - z) * n + z * a;
        hout[(size_t)node * H + j] = hv;
        if (wsplit) {
            __half sh, sl;
            split2s(hv, ASCALE, sh, sl);
            size_t o = (size_t)node * H + j;
            g_xs[0][o] = sh; g_xs[1][o] = sl;
        }
    }
}

// ---------------- launch -----------------------------------------------------
extern "C" void kernel_launch(void* const* d_in, const int* in_sizes, int n_in,
                              void* d_out, int out_size) {
    const float* V   = (const float*)d_in[0];
    const int*   E   = (const int*)d_in[1];
    const float* dw  = (const float*)d_in[2];
    const float* db  = (const float*)d_in[3];
    const float* wih = (const float*)d_in[4];
    const float* whh = (const float*)d_in[5];
    const float* bih = (const float*)d_in[6];
    const float* bhh = (const float*)d_in[7];
    float* out = (float*)d_out;

    float *p_h1, *p_gi, *p_gh, *p_m0, *p_c0;
    __half *p_xs, *p_aggs, *p_ws;
    int *p_cnt, *p_off, *p_order;
    cudaGetSymbolAddress((void**)&p_h1,  g_h1);
    cudaGetSymbolAddress((void**)&p_gi,  g_gi);
    cudaGetSymbolAddress((void**)&p_gh,  g_gh);
    cudaGetSymbolAddress((void**)&p_m0,  g_m0);
    cudaGetSymbolAddress((void**)&p_c0,  g_c0);
    cudaGetSymbolAddress((void**)&p_xs,  g_xs);
    cudaGetSymbolAddress((void**)&p_aggs, g_aggs);
    cudaGetSymbolAddress((void**)&p_ws,  g_ws);
    cudaGetSymbolAddress((void**)&p_cnt, g_cnt);
    cudaGetSymbolAddress((void**)&p_off, g_off);
    cudaGetSymbolAddress((void**)&p_order, g_order);

    cudaFuncSetAttribute(gemm_mma, cudaFuncAttributeMaxDynamicSharedMemorySize, SMEM_TOT);

    // ---- fork side stream for the schedule chain (independent of weights) ----
    cudaStream_t s2;
    cudaStreamCreate(&s2);
    cudaEvent_t evA, evB, evGI1, evG[NL];
    cudaEventCreateWithFlags(&evA, cudaEventDisableTiming);
    cudaEventCreateWithFlags(&evB, cudaEventDisableTiming);
    cudaEventCreateWithFlags(&evGI1, cudaEventDisableTiming);
    for (int s = 0; s < NL; s++) cudaEventCreateWithFlags(&evG[s], cudaEventDisableTiming);

    cudaEventRecord(evA, 0);
    cudaStreamWaitEvent(s2, evA, 0);

    k_init<<<256, 256, 0, s2>>>();
    for (int p = 0; p < NL - 1; p++) k_relax<<<1024, 256, 0, s2>>>(E);
    k_indeg<<<1024, 256, 0, s2>>>(E);
    k_count<<<256, 256, 0, s2>>>();
    k_off8<<<1, 1, 0, s2>>>();
    k_scan<<<1, 1024, 0, s2>>>();
    k_scatter_node<<<256, 256, 0, s2>>>();
    k_scatter_edge<<<1024, 256, 0, s2>>>(E);
    cudaEventRecord(evB, s2);
    // (stream/events intentionally not destroyed: holds no device memory)

    // ---- main stream: fused weights + W splits (overlaps schedule) ----
    k_prep<<<H3, 256>>>(wih, dw);
    k_prep_c<<<3, 256>>>(wih, db, bih);

    const int WN4 = (H3 * H) / 4;
    const size_t WPL = (size_t)H3 * H;
    k_split<<<512, 256>>>(p_m0, p_ws + 0 * WPL, p_ws + 1 * WPL, 1.0f, WN4);
    k_split<<<512, 256>>>(wih + WPL, p_ws + 2 * WPL, p_ws + 3 * WPL, 1.0f, WN4);
    k_split<<<512, 256>>>(whh, p_ws + 4 * WPL, p_ws + 5 * WPL, 1.0f, WN4);
    k_split<<<512, 256>>>(whh + WPL, p_ws + 6 * WPL, p_ws + 7 * WPL, 1.0f, WN4);

    const size_t XPL = (size_t)NP * H;
    k_split<<<1024, 256>>>(V, p_xs, p_xs + XPL, ASCALE, (NN * H) / 4);

    const __half* wgi1 = p_ws + 2 * WPL;

    // =========================== layer 0 ===========================
    {
        const float* bhh_l = bhh;
        // gi0 = V @ m0^T + c0 (all nodes, dense rows)
        gemm_mma<<<1184, 256, SMEM_TOT>>>(p_xs, p_xs + XPL,
                                          p_ws, p_ws + WPL,
                                          p_c0, p_gi, nullptr, nullptr, nullptr,
                                          NN, H3);

        // join the schedule before its first consumer
        cudaStreamWaitEvent(0, evB, 0);

        for (int s = 0; s < NL; s++) {
            if (s > 0) {
                k_gather<<<1024, 256>>>(p_h1, s);
                gemm_mma<<<592, 256, SMEM_TOT>>>(p_aggs, p_aggs + XPL,
                                                 p_ws + 4 * WPL, p_ws + 5 * WPL,
                                                 bhh_l, p_gh, nullptr,
                                                 p_off + s, p_cnt + s, 0, H3);
                k_gru<<<2048, 256>>>(p_h1, s, p_gh, 1, 1);
            } else {
                k_gru<<<2048, 256>>>(p_h1, 0, bhh_l, 0, 1);
            }
            // side stream: gi1 chunk for level-s rows (overlaps later sweeps)
            cudaEventRecord(evG[s], 0);
            cudaStreamWaitEvent(s2, evG[s], 0);
            gemm_mma<<<592, 256, SMEM_TOT, s2>>>(p_xs, p_xs + XPL,
                                                 wgi1, wgi1 + WPL,
                                                 bih + H3, p_gi, p_order,
                                                 p_off + s, p_cnt + s, 0, H3);
        }
        cudaEventRecord(evGI1, s2);
    }

    // =========================== layer 1 ===========================
    {
        const float* bhh_l = bhh + H3;
        cudaStreamWaitEvent(0, evGI1, 0);   // all gi1 chunks done

        k_gru<<<2048, 256>>>(out, 0, bhh_l, 0, 0);
        for (int s = 1; s < NL; s++) {
            k_gather<<<1024, 256>>>(out, s);
            gemm_mma<<<592, 256, SMEM_TOT>>>(p_aggs, p_aggs + XPL,
                                             p_ws + 6 * WPL, p_ws + 7 * WPL,
                                             bhh_l, p_gh, nullptr,
                                             p_off + s, p_cnt + s, 0, H3);
            k_gru<<<2048, 256>>>(out, s, p_gh, 1, 0);
        }
    }
}